// round 10
// baseline (speedup 1.0000x reference)
#include <cuda_runtime.h>
#include <cuda_fp16.h>
#include <math.h>
#include <float.h>

#define NH 8
#define SEQ 4096
#define DH 128
#define LQ 64
#define VTOPK 1024
#define STOPK 2048
#define FORCE_V 30
#define FORCE_S 100
#define SCALE 0.08838834764831845f
#define NW (SEQ / 32)
#define QS_STRIDE 132
#define NPAIR (NH * SEQ * DH / 2)

// ---------------- device scratch ----------------
__device__ float    g_probs[NH * LQ * SEQ];
__device__ float    g_rowinv[NH * LQ];
__device__ float    g_vert [NH * SEQ];
__device__ float    g_slash[NH * SEQ];
__device__ unsigned g_vbits[NH * NW];
__device__ unsigned g_sbits[NH * NW];
// fp16, 2 elems packed per u32 (low = even index)
__device__ unsigned g_q[NPAIR], g_k[NPAIR], g_v[NPAIR];

// ---------------- helpers ----------------
__device__ __forceinline__ void cpa16(unsigned dst, const void* src) {
    asm volatile("cp.async.cg.shared.global [%0], [%1], 16;\n" :: "r"(dst), "l"(src));
}
__device__ __forceinline__ void cpa_commit() { asm volatile("cp.async.commit_group;\n" ::); }
__device__ __forceinline__ void cpa_wait0()  { asm volatile("cp.async.wait_group 0;\n" ::); }

__device__ __forceinline__ void ldsm4(unsigned* r, unsigned a) {
    asm volatile("ldmatrix.sync.aligned.m8n8.x4.shared.b16 {%0,%1,%2,%3}, [%4];"
        : "=r"(r[0]), "=r"(r[1]), "=r"(r[2]), "=r"(r[3]) : "r"(a));
}
__device__ __forceinline__ void ldsm4t(unsigned* r, unsigned a) {
    asm volatile("ldmatrix.sync.aligned.m8n8.x4.trans.shared.b16 {%0,%1,%2,%3}, [%4];"
        : "=r"(r[0]), "=r"(r[1]), "=r"(r[2]), "=r"(r[3]) : "r"(a));
}
__device__ __forceinline__ void mma16(float* d, const unsigned* a, unsigned b0, unsigned b1) {
    asm volatile("mma.sync.aligned.m16n8k16.row.col.f32.f16.f16.f32 "
        "{%0,%1,%2,%3}, {%4,%5,%6,%7}, {%8,%9}, {%0,%1,%2,%3};"
        : "+f"(d[0]), "+f"(d[1]), "+f"(d[2]), "+f"(d[3])
        : "r"(a[0]), "r"(a[1]), "r"(a[2]), "r"(a[3]), "r"(b0), "r"(b1));
}
__device__ __forceinline__ unsigned pk2h(float x, float y) {
    __half2 t = __floats2half2_rn(x, y);
    return *(unsigned*)&t;
}

// allow words for one query row: local key cols c=0..63 of this 64-key tile.
// D = row - jb (query-key distance at c=0). sbm must be padded (>= NW+2 words).
__device__ __forceinline__ void build_allow(int D, const unsigned* sbm,
                                            unsigned vlo, unsigned vhi,
                                            unsigned& alo, unsigned& ahi) {
    if (D < 0) { alo = 0u; ahi = 0u; return; }
    unsigned clo = (D >= 31) ? 0xffffffffu : ((2u << D) - 1u);
    unsigned chi = (D >= 63) ? 0xffffffffu : ((D >= 32) ? ((2u << (D - 32)) - 1u) : 0u);
    unsigned rlo, rhi;
    int ls = D - 31;
    if (ls >= 0) rlo = __brev(__funnelshift_r(sbm[ls >> 5], sbm[(ls >> 5) + 1], ls & 31));
    else         rlo = __brev(sbm[0] << (31 - D));
    int hs = D - 63;
    if (hs >= 0)      rhi = __brev(__funnelshift_r(sbm[hs >> 5], sbm[(hs >> 5) + 1], hs & 31));
    else if (D >= 32) rhi = __brev(sbm[0] << (63 - D));
    else              rhi = 0u;
    alo = (vlo | rlo) & clo;
    ahi = (vhi | rhi) & chi;
}

// ---------------- prep: q*scale, k, v -> fp16 ----------------
__global__ void prep_kernel(const float* __restrict__ q, const float* __restrict__ k,
                            const float* __restrict__ v) {
    int i = blockIdx.x * 256 + threadIdx.x;
    if (i >= NPAIR) return;
    float2 a = ((const float2*)q)[i];
    g_q[i] = pk2h(a.x * SCALE, a.y * SCALE);
    a = ((const float2*)k)[i];
    g_k[i] = pk2h(a.x, a.y);
    a = ((const float2*)v)[i];
    g_v[i] = pk2h(a.x, a.y);
}

// ---------------- kernel A: exp-scores for last 64 queries ----------------
__global__ void pattern_kernel(const float* __restrict__ q, const float* __restrict__ k) {
    extern __shared__ float psm[];
    float* Qs = psm;
    float* Ks = Qs + 64 * QS_STRIDE;
    int h = blockIdx.y, j0 = blockIdx.x * 128;
    int tid = threadIdx.x, ty = tid >> 4, tx = tid & 15;

    for (int e = tid; e < 64 * 32; e += 256) {
        int r = e >> 5, c = e & 31;
        float4 t = *(const float4*)&q[((size_t)(h * SEQ + SEQ - LQ + r)) * DH + (c << 2)];
        t.x *= SCALE; t.y *= SCALE; t.z *= SCALE; t.w *= SCALE;
        *(float4*)&Qs[r * QS_STRIDE + (c << 2)] = t;
    }
    for (int e = tid; e < 128 * 32; e += 256) {
        int r = e >> 5, c = e & 31;
        *(float4*)&Ks[r * 128 + ((c ^ (r >> 2)) << 2)] =
            *(const float4*)&k[((size_t)(h * SEQ + j0 + r)) * DH + (c << 2)];
    }
    __syncthreads();

    float s[4][8];
    #pragma unroll
    for (int a = 0; a < 4; a++)
        #pragma unroll
        for (int b = 0; b < 8; b++) s[a][b] = 0.f;

    #pragma unroll 4
    for (int c = 0; c < 32; c++) {
        float4 qv[4], kv[8];
        #pragma unroll
        for (int a = 0; a < 4; a++)
            qv[a] = *(const float4*)&Qs[(ty * 4 + a) * QS_STRIDE + (c << 2)];
        #pragma unroll
        for (int b = 0; b < 8; b++) {
            int r = tx * 8 + b;
            kv[b] = *(const float4*)&Ks[r * 128 + ((c ^ (r >> 2)) << 2)];
        }
        #pragma unroll
        for (int a = 0; a < 4; a++)
            #pragma unroll
            for (int b = 0; b < 8; b++)
                s[a][b] += qv[a].x * kv[b].x + qv[a].y * kv[b].y
                         + qv[a].z * kv[b].z + qv[a].w * kv[b].w;
    }
    #pragma unroll
    for (int a = 0; a < 4; a++) {
        int row = ty * 4 + a, qpos = SEQ - LQ + row;
        float p[8];
        #pragma unroll
        for (int b = 0; b < 8; b++) {
            int j = j0 + tx * 8 + b;
            p[b] = (j <= qpos) ? __expf(s[a][b]) : 0.f;
        }
        float* dst = &g_probs[((size_t)(h * LQ + row)) * SEQ + j0 + tx * 8];
        *(float4*)&dst[0] = make_float4(p[0], p[1], p[2], p[3]);
        *(float4*)&dst[4] = make_float4(p[4], p[5], p[6], p[7]);
    }
}

// ---------------- kernel B1: deterministic row sums ----------------
__global__ void rowsum_kernel() {
    int b = blockIdx.x;
    int h = b >> 6, r = b & 63;
    const float* rowp = &g_probs[((size_t)(h * LQ + r)) * SEQ];
    int tid = threadIdx.x;              // 128
    float s0 = 0.f, s1 = 0.f;
    for (int j = tid; j < SEQ; j += 256) { s0 += rowp[j]; s1 += rowp[j + 128]; }
    __shared__ float red[128];
    red[tid] = s0 + s1; __syncthreads();
    #pragma unroll
    for (int st = 64; st > 0; st >>= 1) {
        if (tid < st) red[tid] += red[tid + st];
        __syncthreads();
    }
    if (tid == 0) g_rowinv[h * LQ + r] = 1.0f / red[0];
}

// ---------------- kernel B2: vertical + slash (ILP accumulators) ----------------
__global__ void reduce_kernel() {
    int h = blockIdx.x, seg = blockIdx.y;   // grid (NH, 32), 128 threads
    int tid = threadIdx.x;
    __shared__ float inv[LQ];
    if (tid < LQ) inv[tid] = g_rowinv[h * LQ + tid];
    __syncthreads();
    const float* pb = &g_probs[(size_t)h * LQ * SEQ];
    int j = seg * 128 + tid;
    float s0 = 0.f, s1 = 0.f, s2 = 0.f, s3 = 0.f;
    #pragma unroll
    for (int lq = 0; lq < LQ; lq += 4) {
        s0 += pb[(size_t)(lq    ) * SEQ + j] * inv[lq];
        s1 += pb[(size_t)(lq + 1) * SEQ + j] * inv[lq + 1];
        s2 += pb[(size_t)(lq + 2) * SEQ + j] * inv[lq + 2];
        s3 += pb[(size_t)(lq + 3) * SEQ + j] * inv[lq + 3];
    }
    g_vert[h * SEQ + j] = (j < FORCE_V) ? INFINITY : ((s0 + s1) + (s2 + s3));
    float t0 = 0.f, t1 = 0.f, t2 = 0.f, t3 = 0.f;
    #pragma unroll
    for (int lq = 0; lq < LQ; lq += 4) {
        int i0 = (SEQ - LQ) + lq - j;
        if (i0 >= 0)     t0 += pb[(size_t)(lq    ) * SEQ + i0    ] * inv[lq];
        if (i0 + 1 >= 0) t1 += pb[(size_t)(lq + 1) * SEQ + i0 + 1] * inv[lq + 1];
        if (i0 + 2 >= 0) t2 += pb[(size_t)(lq + 2) * SEQ + i0 + 2] * inv[lq + 2];
        if (i0 + 3 >= 0) t3 += pb[(size_t)(lq + 3) * SEQ + i0 + 3] * inv[lq + 3];
    }
    g_slash[h * SEQ + j] = (j < FORCE_S) ? INFINITY : ((t0 + t1) + (t2 + t3));
}

// ---------------- kernel C: exact top-k via radix select ----------------
__global__ void topk_kernel() {
    int which = blockIdx.x, h = blockIdx.y;
    const float* arr = which ? &g_slash[h * SEQ] : &g_vert[h * SEQ];
    unsigned*   bits = which ? &g_sbits[h * NW]  : &g_vbits[h * NW];
    const int K = which ? STOPK : VTOPK;

    __shared__ unsigned vals[SEQ];
    __shared__ unsigned hist[256];
    __shared__ unsigned s_prefix;
    __shared__ int s_rem;
    __shared__ unsigned gtw[NW], eqw[NW], wcnt[NW], psum[NW];
    int tid = threadIdx.x;              // 256

    for (int i = tid; i < SEQ; i += 256) vals[i] = __float_as_uint(arr[i]);
    __syncthreads();

    unsigned prefix = 0; int remaining = K;
    #pragma unroll
    for (int pass = 3; pass >= 0; pass--) {
        int shift = pass * 8;
        hist[tid] = 0u;
        __syncthreads();
        unsigned long long ph = (unsigned long long)prefix >> (shift + 8);
        for (int i = tid; i < SEQ; i += 256) {
            unsigned v = vals[i];
            if (((unsigned long long)v >> (shift + 8)) == ph)
                atomicAdd(&hist[(v >> shift) & 255u], 1u);
        }
        __syncthreads();
        if (tid == 0) {
            int cum = 0, b = 255;
            for (; b > 0; b--) {
                cum += (int)hist[b];
                if (cum >= remaining) break;
            }
            if (cum < remaining) cum += (int)hist[0];
            s_rem = remaining - (cum - (int)hist[b]);
            s_prefix = prefix | ((unsigned)b << shift);
        }
        __syncthreads();
        prefix = s_prefix; remaining = s_rem;
        __syncthreads();
    }

    if (tid < NW) {
        unsigned gm = 0, em = 0;
        #pragma unroll 8
        for (int b = 0; b < 32; b++) {
            unsigned v = vals[tid * 32 + b];
            gm |= (v > prefix ? 1u : 0u) << b;
            em |= (v == prefix ? 1u : 0u) << b;
        }
        gtw[tid] = gm; eqw[tid] = em; wcnt[tid] = __popc(em);
    }
    __syncthreads();
    if (tid == 0) {
        unsigned run = 0;
        for (int w = 0; w < NW; w++) { psum[w] = run; run += wcnt[w]; }
    }
    __syncthreads();
    if (tid < NW) {
        unsigned em = eqw[tid], sel = 0;
        int rank = (int)psum[tid];
        while (em) {
            int b = __ffs(em) - 1;
            if (rank < remaining) sel |= 1u << b;
            rank++;
            em &= em - 1;
        }
        bits[tid] = gtw[tid] | sel;
    }
}

// ---------------- kernel D: tensor-core masked flash attention ----------------
// 128-row q tiles. smem: Q 0..32K, vb@32768, sb@33280 (NW+4 words padded),
// stages @34816: each 32K = K(16K) V(16K). total 100352.
#define SM_Q  0
#define SM_VB 32768
#define SM_SB 33280
#define SM_ST 34816
#define SM_STSZ 32768
#define FL_BYTES (SM_ST + 2 * SM_STSZ)

__device__ __forceinline__ void load_stage(unsigned st, size_t hb, int jb, int tid) {
    #pragma unroll
    for (int i = 0; i < 8; i++) {
        int e = tid + i * 256;          // 0..2047
        int arr = e >> 10;              // 0:K 1:V
        int x = e & 1023;
        int r = x >> 4, c = x & 15;
        unsigned off = (unsigned)(r * 256 + ((c ^ (r & 7)) << 4));
        const unsigned* src = (arr ? g_v : g_k) + hb + (size_t)(jb + r) * 64 + c * 4;
        cpa16(st + (unsigned)arr * 16384u + off, src);
    }
}

__global__ void __launch_bounds__(256, 1)
flash_mma_kernel(float* __restrict__ out) {
    extern __shared__ unsigned char smem[];
    const unsigned sb0 = (unsigned)__cvta_generic_to_shared(smem);
    unsigned* vbm = (unsigned*)(smem + SM_VB);
    unsigned* sbm = (unsigned*)(smem + SM_SB);

    int bid = blockIdx.x;
    int h   = bid & 7;
    int itb = 31 - (bid >> 3);          // heavy-first
    int tid = threadIdx.x, lane = tid & 31, w = tid >> 5;
    int g = lane >> 2, t = lane & 3;
    const int qr0 = w * 16;
    const int i0g = itb * 128;
    const int iA = i0g + qr0 + g;
    const int it2 = 2 * itb + 1;
    const size_t hb = (size_t)h * SEQ * 64;

    if (tid < NW)            vbm[tid]      = g_vbits[h * NW + tid];
    else if (tid < 2 * NW)   sbm[tid - NW] = g_sbits[h * NW + tid - NW];
    if (tid < 4)             sbm[NW + tid] = 0u;     // pad for funnel reads

    // Q tile (128 rows) + stage 0, one commit group
    #pragma unroll
    for (int i = 0; i < 8; i++) {
        int e = tid + i * 256;          // 0..2047 -> Q rows
        int r = e >> 4, c = e & 15;
        unsigned off = (unsigned)(r * 256 + ((c ^ (r & 7)) << 4));
        cpa16(sb0 + SM_Q + off, &g_q[hb + (size_t)(i0g + r) * 64 + c * 4]);
    }
    load_stage(sb0 + SM_ST, hb, 0, tid);
    cpa_commit();
    cpa_wait0();
    __syncthreads();

    int am = (lane >> 3) & 1, ar = lane & 7, ac = lane >> 4;

    // hoisted Q fragments (invariant across jt)
    unsigned Qh[8][4];
    #pragma unroll
    for (int ks = 0; ks < 8; ks++) {
        int row = qr0 + am * 8 + ar, ch = ks * 2 + ac;
        ldsm4(Qh[ks], sb0 + SM_Q + row * 256 + ((ch ^ (row & 7)) << 4));
    }

    float O[16][4];
    #pragma unroll
    for (int o = 0; o < 16; o++) { O[o][0]=0;O[o][1]=0;O[o][2]=0;O[o][3]=0; }
    float lg = 0.f, lg8 = 0.f;

    for (int jt = 0; jt <= it2; jt++) {
        if (jt > 0) { cpa_wait0(); __syncthreads(); }
        unsigned st = sb0 + SM_ST + (jt & 1) * SM_STSZ;
        if (jt < it2) {
            load_stage(sb0 + SM_ST + ((jt + 1) & 1) * SM_STSZ, hb, (jt + 1) * 64, tid);
            cpa_commit();
        }

        // ---- QK: S[16 rows][64 keys] per warp ----
        float S[8][4];
        #pragma unroll
        for (int n = 0; n < 8; n++) { S[n][0]=0;S[n][1]=0;S[n][2]=0;S[n][3]=0; }

        #pragma unroll
        for (int ks = 0; ks < 8; ks++) {
            #pragma unroll
            for (int kt = 0; kt < 4; kt++) {
                unsigned bh[4];
                int row = kt * 16 + am * 8 + ar, ch = ks * 2 + ac;
                ldsm4(bh, st + row * 256 + ((ch ^ (row & 7)) << 4));
                mma16(S[kt*2],   Qh[ks], bh[0], bh[2]);
                mma16(S[kt*2+1], Qh[ks], bh[1], bh[3]);
            }
        }

        // ---- mask (bit-parallel) + exp (max-free) + direct half2 pack ----
        int jb = jt * 64;
        unsigned vlo = vbm[jb >> 5], vhi = vbm[(jb >> 5) + 1];
        unsigned aloA, ahiA, aloB, ahiB;
        build_allow(iA - jb,     sbm, vlo, vhi, aloA, ahiA);
        build_allow(iA - jb + 8, sbm, vlo, vhi, aloB, ahiB);

        unsigned Ph2[8][2];
        #pragma unroll
        for (int n = 0; n < 8; n++) {
            int sh = (n & 3) * 8 + 2 * t;
            unsigned aA = ((n < 4) ? aloA : ahiA) >> sh;
            unsigned aB = ((n < 4) ? aloB : ahiB) >> sh;
            float p0 = (aA & 1u) ? __expf(S[n][0]) : 0.f;
            float p1 = (aA & 2u) ? __expf(S[n][1]) : 0.f;
            float p2 = (aB & 1u) ? __expf(S[n][2]) : 0.f;
            float p3 = (aB & 2u) ? __expf(S[n][3]) : 0.f;
            __half2 h01 = __floats2half2_rn(p0, p1);
            __half2 h23 = __floats2half2_rn(p2, p3);
            float2 f01 = __half22float2(h01);
            float2 f23 = __half22float2(h23);
            lg  += f01.x + f01.y;
            lg8 += f23.x + f23.y;
            Ph2[n][0] = *(unsigned*)&h01;
            Ph2[n][1] = *(unsigned*)&h23;
        }

        // ---- PV (fp16 P x fp16 V) ----
        #pragma unroll
        for (int kp = 0; kp < 4; kp++) {
            unsigned aph[4] = { Ph2[kp*2][0], Ph2[kp*2][1], Ph2[kp*2+1][0], Ph2[kp*2+1][1] };
            #pragma unroll
            for (int n2 = 0; n2 < 8; n2++) {
                unsigned vh4[4];
                int row = kp * 16 + am * 8 + ar, ch = n2 * 2 + ac;
                ldsm4t(vh4, st + 16384 + row * 256 + ((ch ^ (row & 7)) << 4));
                mma16(O[n2*2],   aph, vh4[0], vh4[1]);
                mma16(O[n2*2+1], aph, vh4[2], vh4[3]);
            }
        }
    }

    // ---- epilogue: per-warp rows, no cross-warp combine ----
    lg  += __shfl_xor_sync(0xffffffffu, lg, 1);  lg  += __shfl_xor_sync(0xffffffffu, lg, 2);
    lg8 += __shfl_xor_sync(0xffffffffu, lg8, 1); lg8 += __shfl_xor_sync(0xffffffffu, lg8, 2);
    float inv0 = 1.0f / lg, inv1 = 1.0f / lg8;
    size_t ob = (size_t)h * SEQ * DH;
    int r0 = i0g + qr0 + g, r1 = r0 + 8;
    #pragma unroll
    for (int o = 0; o < 16; o++) {
        *(float2*)&out[ob + (size_t)r0 * DH + o * 8 + 2 * t] =
            make_float2(O[o][0] * inv0, O[o][1] * inv0);
        *(float2*)&out[ob + (size_t)r1 * DH + o * 8 + 2 * t] =
            make_float2(O[o][2] * inv1, O[o][3] * inv1);
    }
}

// ---------------- launch ----------------
extern "C" void kernel_launch(void* const* d_in, const int* in_sizes, int n_in,
                              void* d_out, int out_size) {
    const float* q = (const float*)d_in[0];
    const float* k = (const float*)d_in[1];
    const float* v = (const float*)d_in[2];
    float* out = (float*)d_out;

    prep_kernel<<<(NPAIR + 255) / 256, 256>>>(q, k, v);

    int psm = (64 * QS_STRIDE + 128 * 128) * 4;
    cudaFuncSetAttribute(pattern_kernel, cudaFuncAttributeMaxDynamicSharedMemorySize, psm);
    pattern_kernel<<<dim3(SEQ / 128, NH), 256, psm>>>(q, k);
    rowsum_kernel<<<NH * LQ, 128>>>();
    reduce_kernel<<<dim3(NH, SEQ / 128), 128>>>();
    topk_kernel<<<dim3(2, NH), 256>>>();

    cudaFuncSetAttribute(flash_mma_kernel, cudaFuncAttributeMaxDynamicSharedMemorySize, FL_BYTES);
    flash_mma_kernel<<<32 * NH, 256, FL_BYTES>>>(out);
}

// round 11
// speedup vs baseline: 1.1785x; 1.1785x over previous
#include <cuda_runtime.h>
#include <cuda_fp16.h>
#include <math.h>
#include <float.h>

#define NH 8
#define SEQ 4096
#define DH 128
#define LQ 64
#define VTOPK 1024
#define STOPK 2048
#define FORCE_V 30
#define FORCE_S 100
#define SCALE 0.08838834764831845f
#define NW (SEQ / 32)
#define QS_STRIDE 132
#define NPAIR (NH * SEQ * DH / 2)

// ---------------- device scratch ----------------
__device__ float    g_probs[NH * LQ * SEQ];
__device__ float    g_rowinv[NH * LQ];
__device__ float    g_vert [NH * SEQ];
__device__ float    g_slash[NH * SEQ];
__device__ unsigned g_vbits[NH * NW];
__device__ unsigned g_sbits[NH * NW];
// fp16, 2 elems packed per u32 (low = even index)
__device__ unsigned g_q[NPAIR], g_k[NPAIR], g_v[NPAIR];

// ---------------- helpers ----------------
__device__ __forceinline__ void cpa16(unsigned dst, const void* src) {
    asm volatile("cp.async.cg.shared.global [%0], [%1], 16;\n" :: "r"(dst), "l"(src));
}
__device__ __forceinline__ void cpa_commit() { asm volatile("cp.async.commit_group;\n" ::); }
__device__ __forceinline__ void cpa_wait0()  { asm volatile("cp.async.wait_group 0;\n" ::); }

__device__ __forceinline__ void ldsm4(unsigned* r, unsigned a) {
    asm volatile("ldmatrix.sync.aligned.m8n8.x4.shared.b16 {%0,%1,%2,%3}, [%4];"
        : "=r"(r[0]), "=r"(r[1]), "=r"(r[2]), "=r"(r[3]) : "r"(a));
}
__device__ __forceinline__ void ldsm4t(unsigned* r, unsigned a) {
    asm volatile("ldmatrix.sync.aligned.m8n8.x4.trans.shared.b16 {%0,%1,%2,%3}, [%4];"
        : "=r"(r[0]), "=r"(r[1]), "=r"(r[2]), "=r"(r[3]) : "r"(a));
}
__device__ __forceinline__ void mma16(float* d, const unsigned* a, unsigned b0, unsigned b1) {
    asm volatile("mma.sync.aligned.m16n8k16.row.col.f32.f16.f16.f32 "
        "{%0,%1,%2,%3}, {%4,%5,%6,%7}, {%8,%9}, {%0,%1,%2,%3};"
        : "+f"(d[0]), "+f"(d[1]), "+f"(d[2]), "+f"(d[3])
        : "r"(a[0]), "r"(a[1]), "r"(a[2]), "r"(a[3]), "r"(b0), "r"(b1));
}
__device__ __forceinline__ unsigned pk2h(float x, float y) {
    __half2 t = __floats2half2_rn(x, y);
    return *(unsigned*)&t;
}

// ---------------- kernel A: exp-scores for last 64 queries (+ fused fp16 prep) ----------------
__global__ void pattern_kernel(const float* __restrict__ q, const float* __restrict__ k,
                               const float* __restrict__ v) {
    extern __shared__ float psm[];
    float* Qs = psm;
    float* Ks = Qs + 64 * QS_STRIDE;
    int h = blockIdx.y, j0 = blockIdx.x * 128;
    int tid = threadIdx.x, ty = tid >> 4, tx = tid & 15;

    for (int e = tid; e < 64 * 32; e += 256) {
        int r = e >> 5, c = e & 31;
        float4 t = *(const float4*)&q[((size_t)(h * SEQ + SEQ - LQ + r)) * DH + (c << 2)];
        t.x *= SCALE; t.y *= SCALE; t.z *= SCALE; t.w *= SCALE;
        *(float4*)&Qs[r * QS_STRIDE + (c << 2)] = t;
    }
    for (int e = tid; e < 128 * 32; e += 256) {
        int r = e >> 5, c = e & 31;
        *(float4*)&Ks[r * 128 + ((c ^ (r >> 2)) << 2)] =
            *(const float4*)&k[((size_t)(h * SEQ + j0 + r)) * DH + (c << 2)];
    }
    __syncthreads();

    float s[4][8];
    #pragma unroll
    for (int a = 0; a < 4; a++)
        #pragma unroll
        for (int b = 0; b < 8; b++) s[a][b] = 0.f;

    #pragma unroll 4
    for (int c = 0; c < 32; c++) {
        float4 qv[4], kv[8];
        #pragma unroll
        for (int a = 0; a < 4; a++)
            qv[a] = *(const float4*)&Qs[(ty * 4 + a) * QS_STRIDE + (c << 2)];
        #pragma unroll
        for (int b = 0; b < 8; b++) {
            int r = tx * 8 + b;
            kv[b] = *(const float4*)&Ks[r * 128 + ((c ^ (r >> 2)) << 2)];
        }
        #pragma unroll
        for (int a = 0; a < 4; a++)
            #pragma unroll
            for (int b = 0; b < 8; b++)
                s[a][b] += qv[a].x * kv[b].x + qv[a].y * kv[b].y
                         + qv[a].z * kv[b].z + qv[a].w * kv[b].w;
    }
    #pragma unroll
    for (int a = 0; a < 4; a++) {
        int row = ty * 4 + a, qpos = SEQ - LQ + row;
        float p[8];
        #pragma unroll
        for (int b = 0; b < 8; b++) {
            int j = j0 + tx * 8 + b;
            p[b] = (j <= qpos) ? __expf(s[a][b]) : 0.f;
        }
        float* dst = &g_probs[((size_t)(h * LQ + row)) * SEQ + j0 + tx * 8];
        *(float4*)&dst[0] = make_float4(p[0], p[1], p[2], p[3]);
        *(float4*)&dst[4] = make_float4(p[4], p[5], p[6], p[7]);
    }

    // fused fp16 prep (grid-stride over all pairs; independent of work above)
    int gblk = blockIdx.y * gridDim.x + blockIdx.x;          // 0..255
    for (int i = gblk * 256 + tid; i < NPAIR; i += 256 * 256) {
        float2 a = ((const float2*)q)[i];
        g_q[i] = pk2h(a.x * SCALE, a.y * SCALE);
        a = ((const float2*)k)[i];
        g_k[i] = pk2h(a.x, a.y);
        a = ((const float2*)v)[i];
        g_v[i] = pk2h(a.x, a.y);
    }
}

// ---------------- kernel B1: deterministic row sums ----------------
__global__ void rowsum_kernel() {
    int b = blockIdx.x;
    int h = b >> 6, r = b & 63;
    const float* rowp = &g_probs[((size_t)(h * LQ + r)) * SEQ];
    int tid = threadIdx.x;              // 128
    float s = 0.f;
    for (int j = tid; j < SEQ; j += 128) s += rowp[j];
    __shared__ float red[128];
    red[tid] = s; __syncthreads();
    #pragma unroll
    for (int st = 64; st > 0; st >>= 1) {
        if (tid < st) red[tid] += red[tid + st];
        __syncthreads();
    }
    if (tid == 0) g_rowinv[h * LQ + r] = 1.0f / red[0];
}

// ---------------- kernel B2: vertical + slash ----------------
__global__ void reduce_kernel() {
    int h = blockIdx.x, seg = blockIdx.y;
    int tid = threadIdx.x;              // 256
    __shared__ float inv[LQ];
    if (tid < LQ) inv[tid] = g_rowinv[h * LQ + tid];
    __syncthreads();
    const float* pb = &g_probs[(size_t)h * LQ * SEQ];
    int j = seg * 256 + tid;
    float s = 0.f;
    #pragma unroll 8
    for (int lq = 0; lq < LQ; lq++) s += pb[(size_t)lq * SEQ + j] * inv[lq];
    g_vert[h * SEQ + j] = (j < FORCE_V) ? INFINITY : s;
    float t = 0.f;
    #pragma unroll 8
    for (int lq = 0; lq < LQ; lq++) {
        int idx = (SEQ - LQ) + lq - j;
        if (idx >= 0) t += pb[(size_t)lq * SEQ + idx] * inv[lq];
    }
    g_slash[h * SEQ + j] = (j < FORCE_S) ? INFINITY : t;
}

// ---------------- kernel C: exact top-k via radix select ----------------
__global__ void topk_kernel() {
    int which = blockIdx.x, h = blockIdx.y;
    const float* arr = which ? &g_slash[h * SEQ] : &g_vert[h * SEQ];
    unsigned*   bits = which ? &g_sbits[h * NW]  : &g_vbits[h * NW];
    const int K = which ? STOPK : VTOPK;

    __shared__ unsigned vals[SEQ];
    __shared__ unsigned hist[256];
    __shared__ unsigned s_prefix;
    __shared__ int s_rem;
    __shared__ unsigned gtw[NW], eqw[NW], wcnt[NW], psum[NW];
    int tid = threadIdx.x;              // 256

    for (int i = tid; i < SEQ; i += 256) vals[i] = __float_as_uint(arr[i]);
    __syncthreads();

    unsigned prefix = 0; int remaining = K;
    #pragma unroll
    for (int pass = 3; pass >= 0; pass--) {
        int shift = pass * 8;
        hist[tid] = 0u;
        __syncthreads();
        unsigned long long ph = (unsigned long long)prefix >> (shift + 8);
        for (int i = tid; i < SEQ; i += 256) {
            unsigned v = vals[i];
            if (((unsigned long long)v >> (shift + 8)) == ph)
                atomicAdd(&hist[(v >> shift) & 255u], 1u);
        }
        __syncthreads();
        if (tid == 0) {
            int cum = 0, b = 255;
            for (; b > 0; b--) {
                cum += (int)hist[b];
                if (cum >= remaining) break;
            }
            if (cum < remaining) cum += (int)hist[0];
            s_rem = remaining - (cum - (int)hist[b]);
            s_prefix = prefix | ((unsigned)b << shift);
        }
        __syncthreads();
        prefix = s_prefix; remaining = s_rem;
        __syncthreads();
    }

    if (tid < NW) {
        unsigned gm = 0, em = 0;
        #pragma unroll 8
        for (int b = 0; b < 32; b++) {
            unsigned v = vals[tid * 32 + b];
            gm |= (v > prefix ? 1u : 0u) << b;
            em |= (v == prefix ? 1u : 0u) << b;
        }
        gtw[tid] = gm; eqw[tid] = em; wcnt[tid] = __popc(em);
    }
    __syncthreads();
    if (tid == 0) {
        unsigned run = 0;
        for (int w = 0; w < NW; w++) { psum[w] = run; run += wcnt[w]; }
    }
    __syncthreads();
    if (tid < NW) {
        unsigned em = eqw[tid], sel = 0;
        int rank = (int)psum[tid];
        while (em) {
            int b = __ffs(em) - 1;
            if (rank < remaining) sel |= 1u << b;
            rank++;
            em &= em - 1;
        }
        bits[tid] = gtw[tid] | sel;
    }
}

// ---------------- kernel D: tensor-core masked flash attention ----------------
// 128-row q tiles. smem: Q 0..32K, vb@32768, sb@33280,
// stages @34816: each 32K = K(16K) V(16K). total 100352.
#define SM_Q  0
#define SM_VB 32768
#define SM_SB 33280
#define SM_ST 34816
#define SM_STSZ 32768
#define FL_BYTES (SM_ST + 2 * SM_STSZ)

__device__ __forceinline__ void load_stage(unsigned st, size_t hb, int jb, int tid) {
    #pragma unroll
    for (int i = 0; i < 8; i++) {
        int e = tid + i * 256;          // 0..2047
        int arr = e >> 10;              // 0:K 1:V
        int x = e & 1023;
        int r = x >> 4, c = x & 15;
        unsigned off = (unsigned)(r * 256 + ((c ^ (r & 7)) << 4));
        const unsigned* src = (arr ? g_v : g_k) + hb + (size_t)(jb + r) * 64 + c * 4;
        cpa16(st + (unsigned)arr * 16384u + off, src);
    }
}

__global__ void __launch_bounds__(256, 1)
flash_mma_kernel(float* __restrict__ out) {
    extern __shared__ unsigned char smem[];
    const unsigned sb0 = (unsigned)__cvta_generic_to_shared(smem);
    unsigned* vbm = (unsigned*)(smem + SM_VB);
    unsigned* sbm = (unsigned*)(smem + SM_SB);

    int bid = blockIdx.x;
    int h   = bid & 7;
    int itb = 31 - (bid >> 3);          // heavy-first
    int tid = threadIdx.x, lane = tid & 31, w = tid >> 5;
    int g = lane >> 2, t = lane & 3;
    const int qr0 = w * 16;
    const int i0g = itb * 128;
    const int iA = i0g + qr0 + g;
    const int it2 = 2 * itb + 1;
    const size_t hb = (size_t)h * SEQ * 64;

    if (tid < NW)            vbm[tid]      = g_vbits[h * NW + tid];
    else if (tid < 2 * NW)   sbm[tid - NW] = g_sbits[h * NW + tid - NW];

    // Q tile (128 rows) + stage 0, one commit group
    #pragma unroll
    for (int i = 0; i < 8; i++) {
        int e = tid + i * 256;          // 0..2047 -> Q rows
        int r = e >> 4, c = e & 15;
        unsigned off = (unsigned)(r * 256 + ((c ^ (r & 7)) << 4));
        cpa16(sb0 + SM_Q + off, &g_q[hb + (size_t)(i0g + r) * 64 + c * 4]);
    }
    load_stage(sb0 + SM_ST, hb, 0, tid);
    cpa_commit();
    cpa_wait0();
    __syncthreads();

    int am = (lane >> 3) & 1, ar = lane & 7, ac = lane >> 4;

    // hoisted Q fragments (invariant across jt)
    unsigned Qh[8][4];
    #pragma unroll
    for (int ks = 0; ks < 8; ks++) {
        int row = qr0 + am * 8 + ar, ch = ks * 2 + ac;
        ldsm4(Qh[ks], sb0 + SM_Q + row * 256 + ((ch ^ (row & 7)) << 4));
    }

    float O[16][4];
    #pragma unroll
    for (int o = 0; o < 16; o++) { O[o][0]=0;O[o][1]=0;O[o][2]=0;O[o][3]=0; }
    float lg = 0.f, lg8 = 0.f;

    for (int jt = 0; jt <= it2; jt++) {
        if (jt > 0) { cpa_wait0(); __syncthreads(); }
        unsigned st = sb0 + SM_ST + (jt & 1) * SM_STSZ;
        if (jt < it2) {
            load_stage(sb0 + SM_ST + ((jt + 1) & 1) * SM_STSZ, hb, (jt + 1) * 64, tid);
            cpa_commit();
        }

        // ---- kt-pipelined QK -> mask/exp -> PV ----
        // Sb double buffer: Sb[cur][0] = S rows for n=2kt, Sb[cur][1] = n=2kt+1
        float Sb[2][2][4];
        int jb = jt * 64;

        // QK for kt = 0
        {
            #pragma unroll
            for (int e = 0; e < 4; e++) { Sb[0][0][e] = 0.f; Sb[0][1][e] = 0.f; }
            #pragma unroll
            for (int ks = 0; ks < 8; ks++) {
                unsigned bh[4];
                int row = am * 8 + ar, ch = ks * 2 + ac;
                ldsm4(bh, st + row * 256 + ((ch ^ (row & 7)) << 4));
                mma16(Sb[0][0], Qh[ks], bh[0], bh[2]);
                mma16(Sb[0][1], Qh[ks], bh[1], bh[3]);
            }
        }

        #pragma unroll
        for (int kt = 0; kt < 4; kt++) {
            int cur = kt & 1, nxt = cur ^ 1;
            // issue QK for kt+1 BEFORE the kt epilogue (fills tensor-pipe latency)
            if (kt < 3) {
                #pragma unroll
                for (int e = 0; e < 4; e++) { Sb[nxt][0][e] = 0.f; Sb[nxt][1][e] = 0.f; }
                #pragma unroll
                for (int ks = 0; ks < 8; ks++) {
                    unsigned bh[4];
                    int row = (kt + 1) * 16 + am * 8 + ar, ch = ks * 2 + ac;
                    ldsm4(bh, st + row * 256 + ((ch ^ (row & 7)) << 4));
                    mma16(Sb[nxt][0], Qh[ks], bh[0], bh[2]);
                    mma16(Sb[nxt][1], Qh[ks], bh[1], bh[3]);
                }
            }

            // ---- mask + exp (round-9 exact math) for kt ----
            #pragma unroll
            for (int nn = 0; nn < 2; nn++) {
                int n = kt * 2 + nn;
                int cb = n * 8 + 2 * t;
                float* S = Sb[cur][nn];
                #pragma unroll
                for (int e = 0; e < 4; e++) {
                    int roff = (e >> 1) * 8, b = e & 1;
                    int j = jb + cb + b;
                    int d = iA + roff - j;
                    unsigned sbit = (d >= 0) ? ((sbm[d >> 5] >> (d & 31)) & 1u) : 0u;
                    unsigned vbit = (vbm[j >> 5] >> (j & 31)) & 1u;
                    bool ok = (d >= 0) && (vbit || sbit);
                    float p = ok ? __expf(S[e]) : 0.f;
                    p = __half2float(__float2half_rn(p));
                    S[e] = p;
                    if (e < 2) lg += p; else lg8 += p;
                }
            }

            // ---- PV for kt ----
            unsigned aph[4];
            aph[0] = pk2h(Sb[cur][0][0], Sb[cur][0][1]);
            aph[1] = pk2h(Sb[cur][0][2], Sb[cur][0][3]);
            aph[2] = pk2h(Sb[cur][1][0], Sb[cur][1][1]);
            aph[3] = pk2h(Sb[cur][1][2], Sb[cur][1][3]);
            #pragma unroll
            for (int n2 = 0; n2 < 8; n2++) {
                unsigned vh4[4];
                int row = kt * 16 + am * 8 + ar, ch = n2 * 2 + ac;
                ldsm4t(vh4, st + 16384 + row * 256 + ((ch ^ (row & 7)) << 4));
                mma16(O[n2*2],   aph, vh4[0], vh4[1]);
                mma16(O[n2*2+1], aph, vh4[2], vh4[3]);
            }
        }
    }

    // ---- epilogue: per-warp rows, no cross-warp combine ----
    lg  += __shfl_xor_sync(0xffffffffu, lg, 1);  lg  += __shfl_xor_sync(0xffffffffu, lg, 2);
    lg8 += __shfl_xor_sync(0xffffffffu, lg8, 1); lg8 += __shfl_xor_sync(0xffffffffu, lg8, 2);
    float inv0 = 1.0f / lg, inv1 = 1.0f / lg8;
    size_t ob = (size_t)h * SEQ * DH;
    int r0 = i0g + qr0 + g, r1 = r0 + 8;
    #pragma unroll
    for (int o = 0; o < 16; o++) {
        *(float2*)&out[ob + (size_t)r0 * DH + o * 8 + 2 * t] =
            make_float2(O[o][0] * inv0, O[o][1] * inv0);
        *(float2*)&out[ob + (size_t)r1 * DH + o * 8 + 2 * t] =
            make_float2(O[o][2] * inv1, O[o][3] * inv1);
    }
}

// ---------------- launch ----------------
extern "C" void kernel_launch(void* const* d_in, const int* in_sizes, int n_in,
                              void* d_out, int out_size) {
    const float* q = (const float*)d_in[0];
    const float* k = (const float*)d_in[1];
    const float* v = (const float*)d_in[2];
    float* out = (float*)d_out;

    int psm = (64 * QS_STRIDE + 128 * 128) * 4;
    cudaFuncSetAttribute(pattern_kernel, cudaFuncAttributeMaxDynamicSharedMemorySize, psm);
    pattern_kernel<<<dim3(SEQ / 128, NH), 256, psm>>>(q, k, v);
    rowsum_kernel<<<NH * LQ, 128>>>();
    reduce_kernel<<<dim3(NH, SEQ / 256), 256>>>();
    topk_kernel<<<dim3(2, NH), 256>>>();

    cudaFuncSetAttribute(flash_mma_kernel, cudaFuncAttributeMaxDynamicSharedMemorySize, FL_BYTES);
    flash_mma_kernel<<<32 * NH, 256, FL_BYTES>>>(out);
}

// round 12
// speedup vs baseline: 1.2419x; 1.0538x over previous
#include <cuda_runtime.h>
#include <cuda_fp16.h>
#include <math.h>
#include <float.h>

#define NH 8
#define SEQ 4096
#define DH 128
#define LQ 64
#define VTOPK 1024
#define STOPK 2048
#define FORCE_V 30
#define FORCE_S 100
#define SCALE 0.08838834764831845f
#define NW (SEQ / 32)
#define QS_STRIDE 132
#define NPAIR (NH * SEQ * DH / 2)

// ---------------- device scratch ----------------
__device__ float    g_probs[NH * LQ * SEQ];
__device__ float    g_rowinv[NH * LQ];
__device__ float    g_vert [NH * SEQ];
__device__ float    g_slash[NH * SEQ];
__device__ unsigned g_vbits[NH * NW];
__device__ unsigned g_sbits[NH * NW];
// fp16, 2 elems packed per u32 (low = even index)
__device__ unsigned g_q[NPAIR], g_k[NPAIR], g_v[NPAIR];

// ---------------- helpers ----------------
__device__ __forceinline__ void cpa16(unsigned dst, const void* src) {
    asm volatile("cp.async.cg.shared.global [%0], [%1], 16;\n" :: "r"(dst), "l"(src));
}
__device__ __forceinline__ void cpa_commit() { asm volatile("cp.async.commit_group;\n" ::); }
__device__ __forceinline__ void cpa_wait0()  { asm volatile("cp.async.wait_group 0;\n" ::); }

__device__ __forceinline__ void ldsm4(unsigned* r, unsigned a) {
    asm volatile("ldmatrix.sync.aligned.m8n8.x4.shared.b16 {%0,%1,%2,%3}, [%4];"
        : "=r"(r[0]), "=r"(r[1]), "=r"(r[2]), "=r"(r[3]) : "r"(a));
}
__device__ __forceinline__ void ldsm4t(unsigned* r, unsigned a) {
    asm volatile("ldmatrix.sync.aligned.m8n8.x4.trans.shared.b16 {%0,%1,%2,%3}, [%4];"
        : "=r"(r[0]), "=r"(r[1]), "=r"(r[2]), "=r"(r[3]) : "r"(a));
}
__device__ __forceinline__ void mma16(float* d, const unsigned* a, unsigned b0, unsigned b1) {
    asm volatile("mma.sync.aligned.m16n8k16.row.col.f32.f16.f16.f32 "
        "{%0,%1,%2,%3}, {%4,%5,%6,%7}, {%8,%9}, {%0,%1,%2,%3};"
        : "+f"(d[0]), "+f"(d[1]), "+f"(d[2]), "+f"(d[3])
        : "r"(a[0]), "r"(a[1]), "r"(a[2]), "r"(a[3]), "r"(b0), "r"(b1));
}
__device__ __forceinline__ unsigned pk2h(float x, float y) {
    __half2 t = __floats2half2_rn(x, y);
    return *(unsigned*)&t;
}

// ---------------- kernel A: exp-scores for last 64 queries (+ fused fp16 prep) ----------------
__global__ void pattern_kernel(const float* __restrict__ q, const float* __restrict__ k,
                               const float* __restrict__ v) {
    extern __shared__ float psm[];
    float* Qs = psm;
    float* Ks = Qs + 64 * QS_STRIDE;
    int h = blockIdx.y, j0 = blockIdx.x * 128;
    int tid = threadIdx.x, ty = tid >> 4, tx = tid & 15;

    for (int e = tid; e < 64 * 32; e += 256) {
        int r = e >> 5, c = e & 31;
        float4 t = *(const float4*)&q[((size_t)(h * SEQ + SEQ - LQ + r)) * DH + (c << 2)];
        t.x *= SCALE; t.y *= SCALE; t.z *= SCALE; t.w *= SCALE;
        *(float4*)&Qs[r * QS_STRIDE + (c << 2)] = t;
    }
    for (int e = tid; e < 128 * 32; e += 256) {
        int r = e >> 5, c = e & 31;
        *(float4*)&Ks[r * 128 + ((c ^ (r >> 2)) << 2)] =
            *(const float4*)&k[((size_t)(h * SEQ + j0 + r)) * DH + (c << 2)];
    }
    __syncthreads();

    float s[4][8];
    #pragma unroll
    for (int a = 0; a < 4; a++)
        #pragma unroll
        for (int b = 0; b < 8; b++) s[a][b] = 0.f;

    #pragma unroll 4
    for (int c = 0; c < 32; c++) {
        float4 qv[4], kv[8];
        #pragma unroll
        for (int a = 0; a < 4; a++)
            qv[a] = *(const float4*)&Qs[(ty * 4 + a) * QS_STRIDE + (c << 2)];
        #pragma unroll
        for (int b = 0; b < 8; b++) {
            int r = tx * 8 + b;
            kv[b] = *(const float4*)&Ks[r * 128 + ((c ^ (r >> 2)) << 2)];
        }
        #pragma unroll
        for (int a = 0; a < 4; a++)
            #pragma unroll
            for (int b = 0; b < 8; b++)
                s[a][b] += qv[a].x * kv[b].x + qv[a].y * kv[b].y
                         + qv[a].z * kv[b].z + qv[a].w * kv[b].w;
    }
    #pragma unroll
    for (int a = 0; a < 4; a++) {
        int row = ty * 4 + a, qpos = SEQ - LQ + row;
        float p[8];
        #pragma unroll
        for (int b = 0; b < 8; b++) {
            int j = j0 + tx * 8 + b;
            p[b] = (j <= qpos) ? __expf(s[a][b]) : 0.f;
        }
        float* dst = &g_probs[((size_t)(h * LQ + row)) * SEQ + j0 + tx * 8];
        *(float4*)&dst[0] = make_float4(p[0], p[1], p[2], p[3]);
        *(float4*)&dst[4] = make_float4(p[4], p[5], p[6], p[7]);
    }

    // fused fp16 prep (grid-stride over all pairs; independent of work above)
    int gblk = blockIdx.y * gridDim.x + blockIdx.x;          // 0..255
    for (int i = gblk * 256 + tid; i < NPAIR; i += 256 * 256) {
        float2 a = ((const float2*)q)[i];
        g_q[i] = pk2h(a.x * SCALE, a.y * SCALE);
        a = ((const float2*)k)[i];
        g_k[i] = pk2h(a.x, a.y);
        a = ((const float2*)v)[i];
        g_v[i] = pk2h(a.x, a.y);
    }
}

// ---------------- kernel B1: deterministic row sums ----------------
__global__ void rowsum_kernel() {
    int b = blockIdx.x;
    int h = b >> 6, r = b & 63;
    const float* rowp = &g_probs[((size_t)(h * LQ + r)) * SEQ];
    int tid = threadIdx.x;              // 128
    float s = 0.f;
    for (int j = tid; j < SEQ; j += 128) s += rowp[j];
    __shared__ float red[128];
    red[tid] = s; __syncthreads();
    #pragma unroll
    for (int st = 64; st > 0; st >>= 1) {
        if (tid < st) red[tid] += red[tid + st];
        __syncthreads();
    }
    if (tid == 0) g_rowinv[h * LQ + r] = 1.0f / red[0];
}

// ---------------- kernel B2: vertical + slash (round-9 body, more blocks) ----------------
__global__ void reduce_kernel() {
    int h = blockIdx.x, seg = blockIdx.y;   // grid (NH, 32), 128 threads
    int tid = threadIdx.x;
    __shared__ float inv[LQ];
    if (tid < LQ) inv[tid] = g_rowinv[h * LQ + tid];
    __syncthreads();
    const float* pb = &g_probs[(size_t)h * LQ * SEQ];
    int j = seg * 128 + tid;
    float s = 0.f;
    #pragma unroll 8
    for (int lq = 0; lq < LQ; lq++) s += pb[(size_t)lq * SEQ + j] * inv[lq];
    g_vert[h * SEQ + j] = (j < FORCE_V) ? INFINITY : s;
    float t = 0.f;
    #pragma unroll 8
    for (int lq = 0; lq < LQ; lq++) {
        int idx = (SEQ - LQ) + lq - j;
        if (idx >= 0) t += pb[(size_t)lq * SEQ + idx] * inv[lq];
    }
    g_slash[h * SEQ + j] = (j < FORCE_S) ? INFINITY : t;
}

// ---------------- kernel C: exact top-k via radix select (parallel scans) ----------------
__global__ void topk_kernel() {
    int which = blockIdx.x, h = blockIdx.y;
    const float* arr = which ? &g_slash[h * SEQ] : &g_vert[h * SEQ];
    unsigned*   bits = which ? &g_sbits[h * NW]  : &g_vbits[h * NW];
    const int K = which ? STOPK : VTOPK;

    __shared__ unsigned vals[SEQ];
    __shared__ unsigned hist[256];
    __shared__ int s_b;
    __shared__ unsigned gtw[NW], eqw[NW], wcnt[NW], scan[NW];
    int tid = threadIdx.x;              // 256

    for (int i = tid; i < SEQ; i += 256) vals[i] = __float_as_uint(arr[i]);
    __syncthreads();

    unsigned prefix = 0; int remaining = K;
    #pragma unroll
    for (int pass = 3; pass >= 0; pass--) {
        int shift = pass * 8;
        hist[tid] = 0u;
        if (tid == 0) s_b = 0;
        __syncthreads();
        unsigned long long ph = (unsigned long long)prefix >> (shift + 8);
        for (int i = tid; i < SEQ; i += 256) {
            unsigned v = vals[i];
            if (((unsigned long long)v >> (shift + 8)) == ph)
                atomicAdd(&hist[(v >> shift) & 255u], 1u);
        }
        __syncthreads();
        // parallel suffix sum: hist[b] := sum of hist[b..255]
        #pragma unroll
        for (int off = 1; off < 256; off <<= 1) {
            unsigned add = (tid + off < 256) ? hist[tid + off] : 0u;
            __syncthreads();
            hist[tid] += add;
            __syncthreads();
        }
        // bucket = largest b with suffix[b] >= remaining (suffix non-increasing in b)
        if ((int)hist[tid] >= remaining) atomicMax(&s_b, tid);
        __syncthreads();
        int b = s_b;
        remaining -= (b < 255) ? (int)hist[b + 1] : 0;
        prefix |= ((unsigned)b << shift);
        __syncthreads();
    }

    if (tid < NW) {
        unsigned gm = 0, em = 0;
        #pragma unroll 8
        for (int b = 0; b < 32; b++) {
            unsigned v = vals[tid * 32 + b];
            gm |= (v > prefix ? 1u : 0u) << b;
            em |= (v == prefix ? 1u : 0u) << b;
        }
        gtw[tid] = gm; eqw[tid] = em;
        wcnt[tid] = __popc(em);
        scan[tid] = __popc(em);
    }
    __syncthreads();
    // parallel inclusive scan over NW words
    #pragma unroll
    for (int off = 1; off < NW; off <<= 1) {
        unsigned add = (tid < NW && tid >= off) ? scan[tid - off] : 0u;
        __syncthreads();
        if (tid < NW) scan[tid] += add;
        __syncthreads();
    }
    if (tid < NW) {
        unsigned em = eqw[tid], sel = 0;
        int rank = (int)(scan[tid] - wcnt[tid]);    // exclusive prefix
        while (em) {
            int b = __ffs(em) - 1;
            if (rank < remaining) sel |= 1u << b;
            rank++;
            em &= em - 1;
        }
        bits[tid] = gtw[tid] | sel;
    }
}

// ---------------- kernel D: tensor-core masked flash attention ----------------
// 128-row q tiles. smem: Q 0..32K, vb@32768, sb@33280,
// stages @34816: each 32K = K(16K) V(16K). total 100352.
#define SM_Q  0
#define SM_VB 32768
#define SM_SB 33280
#define SM_ST 34816
#define SM_STSZ 32768
#define FL_BYTES (SM_ST + 2 * SM_STSZ)

__device__ __forceinline__ void load_stage(unsigned st, size_t hb, int jb, int tid) {
    #pragma unroll
    for (int i = 0; i < 8; i++) {
        int e = tid + i * 256;          // 0..2047
        int arr = e >> 10;              // 0:K 1:V
        int x = e & 1023;
        int r = x >> 4, c = x & 15;
        unsigned off = (unsigned)(r * 256 + ((c ^ (r & 7)) << 4));
        const unsigned* src = (arr ? g_v : g_k) + hb + (size_t)(jb + r) * 64 + c * 4;
        cpa16(st + (unsigned)arr * 16384u + off, src);
    }
}

__global__ void __launch_bounds__(256, 1)
flash_mma_kernel(float* __restrict__ out) {
    extern __shared__ unsigned char smem[];
    const unsigned sb0 = (unsigned)__cvta_generic_to_shared(smem);
    unsigned* vbm = (unsigned*)(smem + SM_VB);
    unsigned* sbm = (unsigned*)(smem + SM_SB);

    int bid = blockIdx.x;
    int h   = bid & 7;
    int itb = 31 - (bid >> 3);          // heavy-first
    int tid = threadIdx.x, lane = tid & 31, w = tid >> 5;
    int g = lane >> 2, t = lane & 3;
    const int qr0 = w * 16;
    const int i0g = itb * 128;
    const int iA = i0g + qr0 + g;
    const int it2 = 2 * itb + 1;
    const size_t hb = (size_t)h * SEQ * 64;

    if (tid < NW)            vbm[tid]      = g_vbits[h * NW + tid];
    else if (tid < 2 * NW)   sbm[tid - NW] = g_sbits[h * NW + tid - NW];

    // Q tile (128 rows) + stage 0, one commit group
    #pragma unroll
    for (int i = 0; i < 8; i++) {
        int e = tid + i * 256;          // 0..2047 -> Q rows
        int r = e >> 4, c = e & 15;
        unsigned off = (unsigned)(r * 256 + ((c ^ (r & 7)) << 4));
        cpa16(sb0 + SM_Q + off, &g_q[hb + (size_t)(i0g + r) * 64 + c * 4]);
    }
    load_stage(sb0 + SM_ST, hb, 0, tid);
    cpa_commit();
    cpa_wait0();
    __syncthreads();

    int am = (lane >> 3) & 1, ar = lane & 7, ac = lane >> 4;

    // hoisted Q fragments (invariant across jt)
    unsigned Qh[8][4];
    #pragma unroll
    for (int ks = 0; ks < 8; ks++) {
        int row = qr0 + am * 8 + ar, ch = ks * 2 + ac;
        ldsm4(Qh[ks], sb0 + SM_Q + row * 256 + ((ch ^ (row & 7)) << 4));
    }

    float O[16][4];
    #pragma unroll
    for (int o = 0; o < 16; o++) { O[o][0]=0;O[o][1]=0;O[o][2]=0;O[o][3]=0; }
    float lg = 0.f, lg8 = 0.f;

    for (int jt = 0; jt <= it2; jt++) {
        if (jt > 0) { cpa_wait0(); __syncthreads(); }
        unsigned st = sb0 + SM_ST + (jt & 1) * SM_STSZ;
        if (jt < it2) {
            load_stage(sb0 + SM_ST + ((jt + 1) & 1) * SM_STSZ, hb, (jt + 1) * 64, tid);
            cpa_commit();
        }

        // ---- kt-pipelined QK -> mask/exp -> PV ----
        float Sb[2][2][4];
        int jb = jt * 64;

        // QK for kt = 0
        {
            #pragma unroll
            for (int e = 0; e < 4; e++) { Sb[0][0][e] = 0.f; Sb[0][1][e] = 0.f; }
            #pragma unroll
            for (int ks = 0; ks < 8; ks++) {
                unsigned bh[4];
                int row = am * 8 + ar, ch = ks * 2 + ac;
                ldsm4(bh, st + row * 256 + ((ch ^ (row & 7)) << 4));
                mma16(Sb[0][0], Qh[ks], bh[0], bh[2]);
                mma16(Sb[0][1], Qh[ks], bh[1], bh[3]);
            }
        }

        #pragma unroll
        for (int kt = 0; kt < 4; kt++) {
            int cur = kt & 1, nxt = cur ^ 1;
            // issue QK for kt+1 BEFORE the kt epilogue (fills tensor-pipe latency)
            if (kt < 3) {
                #pragma unroll
                for (int e = 0; e < 4; e++) { Sb[nxt][0][e] = 0.f; Sb[nxt][1][e] = 0.f; }
                #pragma unroll
                for (int ks = 0; ks < 8; ks++) {
                    unsigned bh[4];
                    int row = (kt + 1) * 16 + am * 8 + ar, ch = ks * 2 + ac;
                    ldsm4(bh, st + row * 256 + ((ch ^ (row & 7)) << 4));
                    mma16(Sb[nxt][0], Qh[ks], bh[0], bh[2]);
                    mma16(Sb[nxt][1], Qh[ks], bh[1], bh[3]);
                }
            }

            // ---- mask + exp for kt ----
            #pragma unroll
            for (int nn = 0; nn < 2; nn++) {
                int n = kt * 2 + nn;
                int cb = n * 8 + 2 * t;
                float* S = Sb[cur][nn];
                #pragma unroll
                for (int e = 0; e < 4; e++) {
                    int roff = (e >> 1) * 8, b = e & 1;
                    int j = jb + cb + b;
                    int d = iA + roff - j;
                    unsigned sbit = (d >= 0) ? ((sbm[d >> 5] >> (d & 31)) & 1u) : 0u;
                    unsigned vbit = (vbm[j >> 5] >> (j & 31)) & 1u;
                    bool ok = (d >= 0) && (vbit || sbit);
                    float p = ok ? __expf(S[e]) : 0.f;
                    p = __half2float(__float2half_rn(p));
                    S[e] = p;
                    if (e < 2) lg += p; else lg8 += p;
                }
            }

            // ---- PV for kt ----
            unsigned aph[4];
            aph[0] = pk2h(Sb[cur][0][0], Sb[cur][0][1]);
            aph[1] = pk2h(Sb[cur][0][2], Sb[cur][0][3]);
            aph[2] = pk2h(Sb[cur][1][0], Sb[cur][1][1]);
            aph[3] = pk2h(Sb[cur][1][2], Sb[cur][1][3]);
            #pragma unroll
            for (int n2 = 0; n2 < 8; n2++) {
                unsigned vh4[4];
                int row = kt * 16 + am * 8 + ar, ch = n2 * 2 + ac;
                ldsm4t(vh4, st + 16384 + row * 256 + ((ch ^ (row & 7)) << 4));
                mma16(O[n2*2],   aph, vh4[0], vh4[1]);
                mma16(O[n2*2+1], aph, vh4[2], vh4[3]);
            }
        }
    }

    // ---- epilogue: per-warp rows, no cross-warp combine ----
    lg  += __shfl_xor_sync(0xffffffffu, lg, 1);  lg  += __shfl_xor_sync(0xffffffffu, lg, 2);
    lg8 += __shfl_xor_sync(0xffffffffu, lg8, 1); lg8 += __shfl_xor_sync(0xffffffffu, lg8, 2);
    float inv0 = 1.0f / lg, inv1 = 1.0f / lg8;
    size_t ob = (size_t)h * SEQ * DH;
    int r0 = i0g + qr0 + g, r1 = r0 + 8;
    #pragma unroll
    for (int o = 0; o < 16; o++) {
        *(float2*)&out[ob + (size_t)r0 * DH + o * 8 + 2 * t] =
            make_float2(O[o][0] * inv0, O[o][1] * inv0);
        *(float2*)&out[ob + (size_t)r1 * DH + o * 8 + 2 * t] =
            make_float2(O[o][2] * inv1, O[o][3] * inv1);
    }
}

// ---------------- launch ----------------
extern "C" void kernel_launch(void* const* d_in, const int* in_sizes, int n_in,
                              void* d_out, int out_size) {
    const float* q = (const float*)d_in[0];
    const float* k = (const float*)d_in[1];
    const float* v = (const float*)d_in[2];
    float* out = (float*)d_out;

    int psm = (64 * QS_STRIDE + 128 * 128) * 4;
    cudaFuncSetAttribute(pattern_kernel, cudaFuncAttributeMaxDynamicSharedMemorySize, psm);
    pattern_kernel<<<dim3(SEQ / 128, NH), 256, psm>>>(q, k, v);
    rowsum_kernel<<<NH * LQ, 128>>>();
    reduce_kernel<<<dim3(NH, SEQ / 128), 128>>>();
    topk_kernel<<<dim3(2, NH), 256>>>();

    cudaFuncSetAttribute(flash_mma_kernel, cudaFuncAttributeMaxDynamicSharedMemorySize, FL_BYTES);
    flash_mma_kernel<<<32 * NH, 256, FL_BYTES>>>(out);
}